// round 17
// baseline (speedup 1.0000x reference)
#include <cuda_runtime.h>
#include <cuda_bf16.h>

// ---------------------------------------------------------------------------
// MS-SSIM loss, 3 scales, 11x11 separable Gaussian (sigma=1.5), zero padding.
// R16: tall 32x64 tile (512 thr, 4 blocks/SM) now for BOTH scale 0 and
//      scale 1 (identical phases345<74,512> instantiation); scale 2 keeps the
//      proven 256-thread 32x32 path in its own small launch.
// ---------------------------------------------------------------------------

#define TILE   32
#define HALO   5
#define SPITCH 44            // raw tile pitch (bf16x2 units), origin x0-6

// padded pyramid dims: left pad 6, right pad 8, top/bottom pad 5
#define PW1 270
#define PH1 266
#define PW2 142
#define PH2 138

// tall tile
#define TY0 64
#define LY0 74

__device__ constexpr float GWC[11] = {
    0.00102838f, 0.00759875f, 0.03600077f, 0.10936069f, 0.21300553f,
    0.26601173f, 0.21300553f, 0.10936069f, 0.03600077f, 0.00759875f,
    0.00102838f
};

#define C1_ 0.0001f
#define C2_ 0.0009f

typedef unsigned long long u64;

__device__ __forceinline__ u64 pack2(float a, float b) {
    u64 r; asm("mov.b64 %0, {%1, %2};" : "=l"(r) : "f"(a), "f"(b)); return r;
}
__device__ __forceinline__ void unpack2(u64 v, float& a, float& b) {
    asm("mov.b64 {%0, %1}, %2;" : "=f"(a), "=f"(b) : "l"(v));
}
__device__ __forceinline__ u64 fma2(u64 a, u64 b, u64 c) {
    u64 d; asm("fma.rn.f32x2 %0, %1, %2, %3;" : "=l"(d) : "l"(a), "l"(b), "l"(c)); return d;
}
__device__ __forceinline__ u64 mul2(u64 a, u64 b) {
    u64 d; asm("mul.rn.f32x2 %0, %1, %2;" : "=l"(d) : "l"(a), "l"(b)); return d;
}
__device__ __forceinline__ u64 add2(u64 a, u64 b) {
    u64 d; asm("add.rn.f32x2 %0, %1, %2;" : "=l"(d) : "l"(a), "l"(b)); return d;
}
// bf16x2 (u,v) -> packed fp32x2 u64 directly: lo = v<<16 (u), hi = v&~0xffff (v).
__device__ __forceinline__ u64 bf2pack(unsigned v) {
    u64 r;
    asm("{\n\t"
        ".reg .b32 lo, hi;\n\t"
        "shl.b32 lo, %1, 16;\n\t"
        "and.b32 hi, %1, 0xffff0000;\n\t"
        "mov.b64 %0, {lo, hi};\n\t"
        "}"
        : "=l"(r) : "r"(v));
    return r;
}

// Pooled pyramids, PADDED layout: element (x,y) of image img lives at
// img*PW*PH + (y+5)*PW + (x+6). Pads are never written -> remain zero.
__device__ __nv_bfloat162 g_s1[64 * PW1 * PH1];
__device__ __nv_bfloat162 g_s2[64 * PW2 * PH2];
__device__ double g_acc[3];   // zero-initialized at load; reset by finalize

// ---------------------------------------------------------------------------
// Phases 3-5, templated on tile rows (LY) and thread count (NT).
// Tile x-origin is x0-6: output col c taps smem cols c+1..c+11; pair
// (c0,c0+1) reads cols c0..c0+13 via 7 LDS.64.
// ---------------------------------------------------------------------------
template <int LY, int NT>
__device__ __forceinline__ void phases345(
    __nv_bfloat162 (*sxy)[SPITCH],
    ulonglong2 (*pAB)[TILE],
    float* red,
    int tx, int ty, int tid, int sidx)
{
    constexpr int NW = NT / 32;
    u64 wp[11];
    #pragma unroll
    for (int k = 0; k < 11; k++) wp[k] = pack2(GWC[k], GWC[k]);

    // ---- horizontal blur: LY*16 items x 2 outputs ----
    #pragma unroll
    for (int i = tid; i < LY * 16; i += NT) {
        const int r  = i >> 4;
        const int cb = i & 15;                       // pair base c0 = 2*cb
        const uint2* row64 = (const uint2*)&sxy[r][0];
        uint2 raw[7];
        #pragma unroll
        for (int m = 0; m < 7; m++)
            raw[m] = row64[cb + m];
        u64 hA0 = 0, hB0 = 0, hA1 = 0, hB1 = 0;
        #pragma unroll
        for (int n = 1; n <= 12; n++) {
            unsigned v = (n & 1) ? raw[n >> 1].y : raw[n >> 1].x;
            u64 p  = bf2pack(v);
            u64 sq = mul2(p, p);
            if (n <= 11) {            // out0: weight w[n-1]
                hA0 = fma2(p,  wp[n - 1], hA0);
                hB0 = fma2(sq, wp[n - 1], hB0);
            }
            if (n >= 2) {             // out1: weight w[n-2]
                hA1 = fma2(p,  wp[n - 2], hA1);
                hB1 = fma2(sq, wp[n - 2], hB1);
            }
        }
        pAB[r][2 * cb]     = make_ulonglong2(hA0, hB0);
        pAB[r][2 * cb + 1] = make_ulonglong2(hA1, hB1);
    }
    __syncthreads();

    // ---- vertical blur + SSIM: 4 output rows per thread, 1 col ----
    u64 mA[4] = {0, 0, 0, 0};   // (mu_u, mu_v)
    u64 mB[4] = {0, 0, 0, 0};   // (E[u^2], E[v^2])
    const int rbase = ty * 4;
    #pragma unroll
    for (int k = 0; k < 14; k++) {
        const int hr = rbase + k;
        ulonglong2 vab = pAB[hr][tx];          // LDS.128
        #pragma unroll
        for (int j = 0; j < 4; j++) {
            const int kk = k - j;
            if (kk >= 0 && kk < 11) {
                mA[j] = fma2(vab.x, wp[kk], mA[j]);
                mB[j] = fma2(vab.y, wp[kk], mB[j]);
            }
        }
    }

    float acc = 0.0f;
    #pragma unroll
    for (int j = 0; j < 4; j++) {
        u64 m2 = mul2(mA[j], mA[j]);           // (mu_u^2, mu_v^2)
        float m2u, m2v; unpack2(m2, m2u, m2v);
        float eu, ev;   unpack2(mB[j], eu, ev);
        float D1 = m2u - m2v;                  // = 4*mu1*mu2
        float S1 = m2u + m2v;                  // = 2*(mu1^2+mu2^2)
        float DE = eu - ev;                    // = 4*E[xy]
        float SE = eu + ev;                    // = 2*(E[x^2]+E[y^2])
        float num = (0.5f * D1 + C1_) * (0.5f * (DE - D1) + C2_);
        float den = (0.5f * S1 + C1_) * (0.5f * (SE - S1) + C2_);
        acc += __fdividef(num, den);
    }

    #pragma unroll
    for (int o = 16; o > 0; o >>= 1)
        acc += __shfl_down_sync(0xffffffffu, acc, o);
    if ((tid & 31) == 0) red[tid >> 5] = acc;
    __syncthreads();
    if (tid < NW) {
        float v = red[tid];
        #pragma unroll
        for (int o = NW / 2; o > 0; o >>= 1)
            v += __shfl_down_sync((unsigned)((1ull << NW) - 1ull), v, o, NW);
        if (tid == 0) atomicAdd(&g_acc[sidx], (double)v);
    }
}

static constexpr int SMEM0_PAB = LY0 * SPITCH * 4;               // 13024
static constexpr int SMEM0_RED = SMEM0_PAB + LY0 * TILE * 16;    // 50912
static constexpr int SMEM0_TOTAL = SMEM0_RED + 64;               // 50976

// ---------------------------------------------------------------------------
// Scale 0: 32x64 tile, 512 threads, dynamic smem. fp32 inputs -> (u,v)
// bf16x2 tile; writes BOTH pooled pyramids (padded layout); then SSIM.
// ---------------------------------------------------------------------------
__global__ __launch_bounds__(512, 4)
void ssim_scale0_kernel(const float* __restrict__ pin, const float* __restrict__ tin)
{
    extern __shared__ char smem[];
    __nv_bfloat162 (*sxy)[SPITCH] =
        reinterpret_cast<__nv_bfloat162(*)[SPITCH]>(smem);
    ulonglong2 (*pAB)[TILE] =
        reinterpret_cast<ulonglong2(*)[TILE]>(smem + SMEM0_PAB);
    float* red = reinterpret_cast<float*>(smem + SMEM0_RED);

    const int tx = threadIdx.x, ty = threadIdx.y;
    const int tid = ty * 32 + tx;
    const int x0 = blockIdx.x * TILE;
    const int y0 = blockIdx.y * TY0;
    const int H = 512, W = 512;
    const long imgBase = (long)blockIdx.z * H * W;

    const bool interior = (x0 >= 8) && (x0 + 40 <= W) &&
                          (y0 >= 8) && (y0 + TY0 + 8 <= H);
    const float* pb = pin + imgBase + (long)(y0 - 5) * W + (x0 - 6);
    const float* tb = tin + imgBase + (long)(y0 - 5) * W + (x0 - 6);
    if (interior) {
        // 74 rows x 22 float2 loads (x origin x0-6, 8B aligned)
        #pragma unroll
        for (int i = tid; i < LY0 * 22; i += 512) {
            const int r = i / 22, c2 = i - r * 22;
            float2 av = __ldg((const float2*)(pb + (long)r * W) + c2);
            float2 bv = __ldg((const float2*)(tb + (long)r * W) + c2);
            __nv_bfloat162 t0 = __floats2bfloat162_rn(av.x + bv.x, av.x - bv.x);
            __nv_bfloat162 t1 = __floats2bfloat162_rn(av.y + bv.y, av.y - bv.y);
            *(uint2*)&sxy[r][2 * c2] =
                make_uint2(*(unsigned*)&t0, *(unsigned*)&t1);
        }
    } else {
        // Border: same vectorized loads, range-predicated.
        const int c2lo = (x0 == 0) ? 3 : 0;
        const int c2hi = (x0 + TILE == W) ? 19 : 22;
        #pragma unroll
        for (int i = tid; i < LY0 * 22; i += 512) {
            const int r = i / 22, c2 = i - r * 22;
            const int gy = y0 + r - 5;
            const bool ok = (gy >= 0) && (gy < H) &&
                            (c2 >= c2lo) && (c2 < c2hi);
            float2 av = make_float2(0.f, 0.f);
            float2 bv = make_float2(0.f, 0.f);
            if (ok) {
                av = __ldg((const float2*)(pb + (long)r * W) + c2);
                bv = __ldg((const float2*)(tb + (long)r * W) + c2);
            }
            __nv_bfloat162 t0 = __floats2bfloat162_rn(av.x + bv.x, av.x - bv.x);
            __nv_bfloat162 t1 = __floats2bfloat162_rn(av.y + bv.y, av.y - bv.y);
            *(uint2*)&sxy[r][2 * c2] =
                make_uint2(*(unsigned*)&t0, *(unsigned*)&t1);
        }
    }
    __syncthreads();

    const u64 quarter2 = pack2(0.25f, 0.25f);

    // 2x2 pool -> g_s1: 32 rows x 16 cols = 512 outputs, one per thread
    {
        const int pr = tid >> 4;            // 0..31
        const int pc = tid & 15;            // 0..15
        const int r = 5 + 2 * pr, c = 6 + 2 * pc;
        u64 s = add2(add2(bf2pack(*(const unsigned*)&sxy[r][c]),
                          bf2pack(*(const unsigned*)&sxy[r][c + 1])),
                     add2(bf2pack(*(const unsigned*)&sxy[r + 1][c]),
                          bf2pack(*(const unsigned*)&sxy[r + 1][c + 1])));
        s = mul2(s, quarter2);
        float u, v; unpack2(s, u, v);
        long poff = (long)blockIdx.z * (PW1 * PH1)
                  + (long)(y0 / 2 + pr + 5) * PW1 + (x0 / 2 + pc + 6);
        g_s1[poff] = __floats2bfloat162_rn(u, v);
    }
    // 4x4 pool -> g_s2: 16 rows x 8 cols = 128 outputs (threads 0..127)
    if (tid < 128) {
        const int pr = tid >> 3;            // 0..15
        const int pc = tid & 7;             // 0..7
        const int r = 5 + 4 * pr, c = 6 + 4 * pc;
        u64 s = 0;
        #pragma unroll
        for (int dr = 0; dr < 4; dr++) {
            u64 rs = add2(add2(bf2pack(*(const unsigned*)&sxy[r + dr][c]),
                               bf2pack(*(const unsigned*)&sxy[r + dr][c + 1])),
                          add2(bf2pack(*(const unsigned*)&sxy[r + dr][c + 2]),
                               bf2pack(*(const unsigned*)&sxy[r + dr][c + 3])));
            s = (dr == 0) ? rs : add2(s, rs);
        }
        s = mul2(s, mul2(quarter2, quarter2));
        float u, v; unpack2(s, u, v);
        long poff = (long)blockIdx.z * (PW2 * PH2)
                  + (long)(y0 / 4 + pr + 5) * PW2 + (x0 / 4 + pc + 6);
        g_s2[poff] = __floats2bfloat162_rn(u, v);
    }

    phases345<LY0, 512>(sxy, pAB, red, tx, ty, tid, 0);
}

// ---------------------------------------------------------------------------
// Scale 1: 32x64 tall tile, 512 threads, dynamic smem. Loads (u,v) bf16x2
// from padded g_s1 (no border branch; pads are zero). grid (8, 4, 64).
// ---------------------------------------------------------------------------
__global__ __launch_bounds__(512, 4)
void ssim_scale1_kernel()
{
    extern __shared__ char smem[];
    __nv_bfloat162 (*sxy)[SPITCH] =
        reinterpret_cast<__nv_bfloat162(*)[SPITCH]>(smem);
    ulonglong2 (*pAB)[TILE] =
        reinterpret_cast<ulonglong2(*)[TILE]>(smem + SMEM0_PAB);
    float* red = reinterpret_cast<float*>(smem + SMEM0_RED);

    const int tx = threadIdx.x, ty = threadIdx.y;
    const int tid = ty * 32 + tx;
    const int x0 = blockIdx.x * TILE;
    const int y0 = blockIdx.y * TY0;

    const __nv_bfloat162* base =
        g_s1 + (long)blockIdx.z * (PW1 * PH1) + (long)y0 * PW1 + x0;

    // 74 rows x 22 uint2 loads; all addresses 8B-aligned (even indices).
    #pragma unroll
    for (int i = tid; i < LY0 * 22; i += 512) {
        const int r = i / 22, c2 = i - r * 22;
        uint2 v = __ldg((const uint2*)(base + (long)r * PW1) + c2);
        *(uint2*)&sxy[r][2 * c2] = v;
    }
    __syncthreads();

    phases345<LY0, 512>(sxy, pAB, red, tx, ty, tid, 1);
}

// ---------------------------------------------------------------------------
// Scale 2: 32x32 tile, 256 threads (proven path). grid (4, 4, 64).
// ---------------------------------------------------------------------------
__global__ __launch_bounds__(256, 7)
void ssim_scale2_kernel()
{
    __shared__ __nv_bfloat162 sxy[42][SPITCH];
    __shared__ ulonglong2 pAB[42][TILE];
    __shared__ float red[8];

    const int tx = threadIdx.x, ty = threadIdx.y;
    const int tid = ty * 32 + tx;
    const int x0 = blockIdx.x * TILE;
    const int y0 = blockIdx.y * TILE;

    const __nv_bfloat162* base =
        g_s2 + (long)blockIdx.z * (PW2 * PH2) + (long)y0 * PW2 + x0;

    // 42 rows x 22 uint2 loads; all addresses 8B-aligned (even indices).
    #pragma unroll
    for (int it = 0; it < 4; it++) {
        const int i = tid + it * 256;
        if (i < 924) {
            const int r = i / 22, c2 = i - r * 22;
            uint2 v = __ldg((const uint2*)(base + (long)r * PW2) + c2);
            *(uint2*)&sxy[r][2 * c2] = v;
        }
    }
    __syncthreads();

    phases345<42, 256>(sxy, pAB, red, tx, ty, tid, 2);
}

__global__ void finalize_kernel(float* __restrict__ out) {
    const double n0 = 64.0 * 512.0 * 512.0;
    const double n1 = 64.0 * 256.0 * 256.0;
    const double n2 = 64.0 * 128.0 * 128.0;
    double ms = 0.5 * (g_acc[0] / n0) + 0.3 * (g_acc[1] / n1) + 0.2 * (g_acc[2] / n2);
    out[0] = (float)(1.0 - ms);
    // reset for the next graph replay (globals start zeroed at module load)
    g_acc[0] = 0.0; g_acc[1] = 0.0; g_acc[2] = 0.0;
}

extern "C" void kernel_launch(void* const* d_in, const int* in_sizes, int n_in,
                              void* d_out, int out_size)
{
    const float* pred = (const float*)d_in[0];
    const float* targ = (const float*)d_in[1];
    float* out = (float*)d_out;

    cudaFuncSetAttribute(ssim_scale0_kernel,
                         cudaFuncAttributeMaxDynamicSharedMemorySize,
                         SMEM0_TOTAL);
    cudaFuncSetAttribute(ssim_scale1_kernel,
                         cudaFuncAttributeMaxDynamicSharedMemorySize,
                         SMEM0_TOTAL);

    ssim_scale0_kernel<<<dim3(16, 8, 64), dim3(32, 16), SMEM0_TOTAL>>>(pred, targ);
    ssim_scale1_kernel<<<dim3(8, 4, 64), dim3(32, 16), SMEM0_TOTAL>>>();
    ssim_scale2_kernel<<<dim3(4, 4, 64), dim3(32, 8)>>>();
    finalize_kernel<<<1, 1>>>(out);
}